// round 2
// baseline (speedup 1.0000x reference)
#include <cuda_runtime.h>
#include <cstdint>

// Problem constants
// B=32, L=512, E=H=512, G=4H=2048, N=2 layers, V=32000
#define NB 32
#define NL 512
#define NH 512
#define NG 2048
#define NLAYERS 2

// Scratch (static device globals -- allocation-free)
__device__ float g_xg[(size_t)NL * NB * NG];      // (L*B, 4H) gate preactivations (input part + bias)
__device__ float g_hseq[(size_t)NL * NB * NH];    // (L*B, H) layer-0 output sequence
__device__ float g_hstate[2 * NH * NB];           // double-buffered h, layout [buf][k][b]
__device__ int   g_bar;                           // global barrier counter

// ---------------------------------------------------------------------------
// init: zero h state + barrier counter
// ---------------------------------------------------------------------------
__global__ void init_kernel() {
    int tid = threadIdx.x;
    for (int i = tid; i < 2 * NH * NB; i += 256) g_hstate[i] = 0.f;
    if (tid == 0) g_bar = 0;
}

// ---------------------------------------------------------------------------
// xg GEMM: xg[m][n] = sum_k A[m][k] * W[n][k] + (bih[n]+bhh[n])
//   m = t*32 + b  (M = 16384), n in [0,2048), K = 512
//   gather=1: A row = emb[tokens[b*512+t]]; gather=0: A row = g_hseq[m]
// 128x128x8 tile, 256 threads, 8x8 microtile.
// ---------------------------------------------------------------------------
__global__ __launch_bounds__(256) void xg_gemm(
    const float* __restrict__ emb,
    const int*   __restrict__ tokens,
    int gather,
    const float* __restrict__ W,        // (2048, 512) row-major
    const float* __restrict__ bih_l,
    const float* __restrict__ bhh_l)
{
    __shared__ float As[8][128];
    __shared__ float Bs[8][128];
    __shared__ float bias_s[128];

    const int tid = threadIdx.x;
    const int n0 = blockIdx.x * 128;
    const int m0 = blockIdx.y * 128;

    if (tid < 128) bias_s[tid] = bih_l[n0 + tid] + bhh_l[n0 + tid];

    const int lr = tid >> 1;          // 0..127 tile row for loading
    const int kq = (tid & 1) * 4;     // 0 or 4

    const float* arow;
    {
        int m = m0 + lr;
        if (gather) {
            int t = m >> 5, b = m & 31;
            int tok = tokens[b * NL + t];
            arow = emb + (size_t)tok * 512;
        } else {
            arow = g_hseq + (size_t)m * 512;
        }
    }
    const float* brow = W + (size_t)(n0 + lr) * 512;

    const int tm = (tid >> 4) * 8;
    const int tn = (tid & 15) * 8;

    float acc[8][8];
#pragma unroll
    for (int i = 0; i < 8; i++)
#pragma unroll
        for (int j = 0; j < 8; j++) acc[i][j] = 0.f;

    for (int k0 = 0; k0 < 512; k0 += 8) {
        float4 av = *(const float4*)(arow + k0 + kq);
        float4 bv = *(const float4*)(brow + k0 + kq);
        __syncthreads();
        As[kq + 0][lr] = av.x; As[kq + 1][lr] = av.y;
        As[kq + 2][lr] = av.z; As[kq + 3][lr] = av.w;
        Bs[kq + 0][lr] = bv.x; Bs[kq + 1][lr] = bv.y;
        Bs[kq + 2][lr] = bv.z; Bs[kq + 3][lr] = bv.w;
        __syncthreads();
#pragma unroll
        for (int kk = 0; kk < 8; kk++) {
            float a[8], b[8];
            *(float4*)(a)     = *(const float4*)(&As[kk][tm]);
            *(float4*)(a + 4) = *(const float4*)(&As[kk][tm + 4]);
            *(float4*)(b)     = *(const float4*)(&Bs[kk][tn]);
            *(float4*)(b + 4) = *(const float4*)(&Bs[kk][tn + 4]);
#pragma unroll
            for (int i = 0; i < 8; i++)
#pragma unroll
                for (int j = 0; j < 8; j++)
                    acc[i][j] += a[i] * b[j];
        }
    }

#pragma unroll
    for (int i = 0; i < 8; i++) {
        float* orow = g_xg + (size_t)(m0 + tm + i) * NG + n0 + tn;
        float4 v0 = make_float4(acc[i][0] + bias_s[tn + 0], acc[i][1] + bias_s[tn + 1],
                                acc[i][2] + bias_s[tn + 2], acc[i][3] + bias_s[tn + 3]);
        float4 v1 = make_float4(acc[i][4] + bias_s[tn + 4], acc[i][5] + bias_s[tn + 5],
                                acc[i][6] + bias_s[tn + 6], acc[i][7] + bias_s[tn + 7]);
        *(float4*)(orow)     = v0;
        *(float4*)(orow + 4) = v1;
    }
}

// ---------------------------------------------------------------------------
// Persistent LSTM recurrence: 128 CTAs x 256 threads, one CTA per 4 hidden
// units (16 gate rows). Weights resident in smem for all 512 steps.
// Per step: stage h (k-major [k][b]) to smem, warps split K (8 x 64),
// 4x4 register tile per lane, smem reduction, fused gates, global spin
// barrier with double-buffered h state.
// ---------------------------------------------------------------------------
__global__ __launch_bounds__(256, 1) void lstm_rec(
    const float* __restrict__ Whh_l,   // (2048, 512)
    int write_seq, int layer,
    float* __restrict__ d_out)
{
    extern __shared__ float sm[];
    float* hs   = sm;                    // 512*32  = 16384 floats  (h, [k][b])
    float* w_s  = hs  + 512 * 32;        // 512*16  = 8192          (Whh^T slice, [k][lr])
    float* red  = w_s + 512 * 16;        // 8*16*32 = 4096          (per-warp partials)
    float* gate = red + 8 * 16 * 32;     // 16*32   = 512
    float* c_s  = gate + 16 * 32;        // 4*32    = 128           (cell state, persistent)

    const int tid = threadIdx.x;
    const int cta = blockIdx.x;          // 0..127 -> units [cta*4, cta*4+4)

    // One-time: load 16 gate rows of Whh, transposed into [k][lr]
    for (int idx = tid; idx < 16 * 512; idx += 256) {
        int lrw = idx >> 9;              // 0..15
        int k   = idx & 511;
        int q = lrw >> 2, u = lrw & 3;
        int row = q * 512 + cta * 4 + u;
        w_s[k * 16 + lrw] = Whh_l[(size_t)row * 512 + k];
    }
    if (tid < 128) c_s[tid] = 0.f;
    __syncthreads();

    const int lane = tid & 31, warp = tid >> 5;
    const int rg = lane >> 3, bg = lane & 7;
    const int k0 = warp * 64;

    // Reduce-phase output assignment (2 per thread)
    const int o0 = tid, o1 = tid + 256;
    const int lr0 = o0 >> 5, b0 = o0 & 31;
    const int lr1 = o1 >> 5, b1 = o1 & 31;
    const int row0 = (lr0 >> 2) * 512 + cta * 4 + (lr0 & 3);
    const int row1 = (lr1 >> 2) * 512 + cta * 4 + (lr1 & 3);

    for (int t = 0; t < NL; t++) {
        // Prefetch xg for this step (independent of h -> overlaps dot products)
        float xg0 = __ldg(g_xg + (size_t)(t * 32 + b0) * NG + row0);
        float xg1 = __ldg(g_xg + (size_t)(t * 32 + b1) * NG + row1);

        // Stage h_{t-1} into smem
        const float* hsrc = g_hstate + (t & 1) * NH * NB;
        for (int i = tid * 4; i < 512 * 32; i += 256 * 4)
            *(float4*)(hs + i) = *(const float4*)(hsrc + i);
        __syncthreads();

        // Dot products: this warp handles K in [k0, k0+64)
        float acc[4][4];
#pragma unroll
        for (int i = 0; i < 4; i++)
#pragma unroll
            for (int j = 0; j < 4; j++) acc[i][j] = 0.f;

#pragma unroll 4
        for (int k = k0; k < k0 + 64; k++) {
            float4 wv = *(const float4*)(w_s + k * 16 + rg * 4);
            float4 hv = *(const float4*)(hs  + k * 32 + bg * 4);
            acc[0][0] += wv.x * hv.x; acc[0][1] += wv.x * hv.y;
            acc[0][2] += wv.x * hv.z; acc[0][3] += wv.x * hv.w;
            acc[1][0] += wv.y * hv.x; acc[1][1] += wv.y * hv.y;
            acc[1][2] += wv.y * hv.z; acc[1][3] += wv.y * hv.w;
            acc[2][0] += wv.z * hv.x; acc[2][1] += wv.z * hv.y;
            acc[2][2] += wv.z * hv.z; acc[2][3] += wv.z * hv.w;
            acc[3][0] += wv.w * hv.x; acc[3][1] += wv.w * hv.y;
            acc[3][2] += wv.w * hv.z; acc[3][3] += wv.w * hv.w;
        }
#pragma unroll
        for (int ri = 0; ri < 4; ri++)
            *(float4*)(red + ((warp * 16 + rg * 4 + ri) * 32 + bg * 4)) =
                make_float4(acc[ri][0], acc[ri][1], acc[ri][2], acc[ri][3]);
        __syncthreads();

        // Cross-warp K reduction + add xg (bias already in xg)
        {
            float s0 = xg0, s1 = xg1;
#pragma unroll
            for (int w = 0; w < 8; w++) {
                s0 += red[(w * 16 + lr0) * 32 + b0];
                s1 += red[(w * 16 + lr1) * 32 + b1];
            }
            gate[lr0 * 32 + b0] = s0;
            gate[lr1 * 32 + b1] = s1;
        }
        __syncthreads();

        // Gates + state update (torch order i, f, g, o; lr = q*4 + u)
        if (tid < 128) {
            int u = tid >> 5, b = tid & 31;
            float gi = gate[(0 + u) * 32 + b];
            float gf = gate[(4 + u) * 32 + b];
            float gg = gate[(8 + u) * 32 + b];
            float go = gate[(12 + u) * 32 + b];
            float ig = 1.f / (1.f + __expf(-gi));
            float fg = 1.f / (1.f + __expf(-gf));
            float cg = tanhf(gg);
            float og = 1.f / (1.f + __expf(-go));
            float c = fg * c_s[tid] + ig * cg;
            c_s[tid] = c;
            float h = og * tanhf(c);
            int j = cta * 4 + u;
            g_hstate[((t + 1) & 1) * NH * NB + j * 32 + b] = h;
            if (write_seq) g_hseq[(size_t)(t * 32 + b) * NH + j] = h;
            if (t == NL - 1) {
                d_out[layer * NB * NH + b * NH + j] = h;                       // hidden
                d_out[NLAYERS * NB * NH + layer * NB * NH + b * NH + j] = c;   // cell
            }
        }
        __syncthreads();

        // Grid-wide barrier (release-acquire via fence + monotonic counter)
        if (tid == 0) {
            __threadfence();
            atomicAdd(&g_bar, 1);
            int target = 128 * (t + 1);
            int v;
            do {
                asm volatile("ld.acquire.gpu.s32 %0, [%1];" : "=r"(v) : "l"(&g_bar));
            } while (v < target);
        }
        __syncthreads();
    }
}

// ---------------------------------------------------------------------------
// Launcher
// ---------------------------------------------------------------------------
extern "C" void kernel_launch(void* const* d_in, const int* in_sizes, int n_in,
                              void* d_out, int out_size) {
    const int*   tokens = (const int*)  d_in[0];
    const float* emb    = (const float*)d_in[1];
    const float* Wih    = (const float*)d_in[2];   // (2, 2048, 512)
    const float* Whh    = (const float*)d_in[3];   // (2, 2048, 512)
    const float* bih    = (const float*)d_in[4];   // (2, 2048)
    const float* bhh    = (const float*)d_in[5];   // (2, 2048)
    float* out = (float*)d_out;

    const int REC_SMEM = (512 * 32 + 512 * 16 + 8 * 16 * 32 + 16 * 32 + 4 * 32) * 4;
    cudaFuncSetAttribute(lstm_rec, cudaFuncAttributeMaxDynamicSharedMemorySize, REC_SMEM);

    dim3 ggrid(NG / 128, (NL * NB) / 128);   // (16, 128)

    // ---- layer 0 ----
    xg_gemm<<<ggrid, 256>>>(emb, tokens, 1, Wih, bih, bhh);
    init_kernel<<<1, 256>>>();
    lstm_rec<<<128, 256, REC_SMEM>>>(Whh, 1, 0, out);

    // ---- layer 1 ----
    xg_gemm<<<ggrid, 256>>>(emb, tokens, 0, Wih + (size_t)NG * NH, bih + NG, bhh + NG);
    init_kernel<<<1, 256>>>();
    lstm_rec<<<128, 256, REC_SMEM>>>(Whh + (size_t)NG * NH, 0, 1, out);
}

// round 3
// speedup vs baseline: 1.0072x; 1.0072x over previous
#include <cuda_runtime.h>
#include <cstdint>

// Problem constants
// B=32, L=512, E=H=512, G=4H=2048, N=2 layers, V=32000
#define NB 32
#define NL 512
#define NH 512
#define NG 2048
#define NLAYERS 2

// Scratch (static device globals -- allocation-free)
__device__ float g_xg[(size_t)NL * NB * NG];      // (L*B, 4H) gate preactivations (input part + bias)
__device__ float g_hseq[(size_t)NL * NB * NH];    // (L*B, H) layer-0 output sequence
__device__ float g_hstate[2 * NH * NB];           // double-buffered h, layout [buf][k][b]
__device__ int   g_bar;                           // global barrier counter

// ---------------------------------------------------------------------------
// init: zero h state + barrier counter
// ---------------------------------------------------------------------------
__global__ void init_kernel() {
    int tid = threadIdx.x;
    for (int i = tid; i < 2 * NH * NB; i += 256) g_hstate[i] = 0.f;
    if (tid == 0) g_bar = 0;
}

// ---------------------------------------------------------------------------
// xg GEMM: xg[m][n] = sum_k A[m][k] * W[n][k] + (bih[n]+bhh[n])
//   m = t*32 + b  (M = 16384), n in [0,2048), K = 512
//   gather=1: A row = emb[tokens[b*512+t]]; gather=0: A row = g_hseq[m]
// 128x128x8 tile, 256 threads, 8x8 microtile.
// ---------------------------------------------------------------------------
__global__ __launch_bounds__(256) void xg_gemm(
    const float* __restrict__ emb,
    const int*   __restrict__ tokens,
    int gather,
    const float* __restrict__ W,        // (2048, 512) row-major
    const float* __restrict__ bih_l,
    const float* __restrict__ bhh_l)
{
    __shared__ float As[8][128];
    __shared__ float Bs[8][128];
    __shared__ float bias_s[128];

    const int tid = threadIdx.x;
    const int n0 = blockIdx.x * 128;
    const int m0 = blockIdx.y * 128;

    if (tid < 128) bias_s[tid] = bih_l[n0 + tid] + bhh_l[n0 + tid];

    const int lr = tid >> 1;          // 0..127 tile row for loading
    const int kq = (tid & 1) * 4;     // 0 or 4

    const float* arow;
    {
        int m = m0 + lr;
        if (gather) {
            int t = m >> 5, b = m & 31;
            int tok = tokens[b * NL + t];
            arow = emb + (size_t)tok * 512;
        } else {
            arow = g_hseq + (size_t)m * 512;
        }
    }
    const float* brow = W + (size_t)(n0 + lr) * 512;

    const int tm = (tid >> 4) * 8;
    const int tn = (tid & 15) * 8;

    float acc[8][8];
#pragma unroll
    for (int i = 0; i < 8; i++)
#pragma unroll
        for (int j = 0; j < 8; j++) acc[i][j] = 0.f;

    for (int k0 = 0; k0 < 512; k0 += 8) {
        float4 av = *(const float4*)(arow + k0 + kq);
        float4 bv = *(const float4*)(brow + k0 + kq);
        __syncthreads();
        As[kq + 0][lr] = av.x; As[kq + 1][lr] = av.y;
        As[kq + 2][lr] = av.z; As[kq + 3][lr] = av.w;
        Bs[kq + 0][lr] = bv.x; Bs[kq + 1][lr] = bv.y;
        Bs[kq + 2][lr] = bv.z; Bs[kq + 3][lr] = bv.w;
        __syncthreads();
#pragma unroll
        for (int kk = 0; kk < 8; kk++) {
            float a[8], b[8];
            *(float4*)(a)     = *(const float4*)(&As[kk][tm]);
            *(float4*)(a + 4) = *(const float4*)(&As[kk][tm + 4]);
            *(float4*)(b)     = *(const float4*)(&Bs[kk][tn]);
            *(float4*)(b + 4) = *(const float4*)(&Bs[kk][tn + 4]);
#pragma unroll
            for (int i = 0; i < 8; i++)
#pragma unroll
                for (int j = 0; j < 8; j++)
                    acc[i][j] += a[i] * b[j];
        }
    }

#pragma unroll
    for (int i = 0; i < 8; i++) {
        float* orow = g_xg + (size_t)(m0 + tm + i) * NG + n0 + tn;
        float4 v0 = make_float4(acc[i][0] + bias_s[tn + 0], acc[i][1] + bias_s[tn + 1],
                                acc[i][2] + bias_s[tn + 2], acc[i][3] + bias_s[tn + 3]);
        float4 v1 = make_float4(acc[i][4] + bias_s[tn + 4], acc[i][5] + bias_s[tn + 5],
                                acc[i][6] + bias_s[tn + 6], acc[i][7] + bias_s[tn + 7]);
        *(float4*)(orow)     = v0;
        *(float4*)(orow + 4) = v1;
    }
}

// ---------------------------------------------------------------------------
// Persistent LSTM recurrence: 128 CTAs x 256 threads, one CTA per 4 hidden
// units (16 gate rows). Weights resident in smem for all 512 steps.
// Per step: stage h (k-major [k][b]) to smem, warps split K (8 x 64),
// 4x4 register tile per lane, smem reduction, fused gates, global spin
// barrier with double-buffered h state.
// ---------------------------------------------------------------------------
__global__ __launch_bounds__(256, 1) void lstm_rec(
    const float* __restrict__ Whh_l,   // (2048, 512)
    int write_seq, int layer,
    float* __restrict__ d_out)
{
    extern __shared__ float sm[];
    float* hs   = sm;                    // 512*32  = 16384 floats  (h, [k][b])
    float* w_s  = hs  + 512 * 32;        // 512*16  = 8192          (Whh^T slice, [k][lr])
    float* red  = w_s + 512 * 16;        // 8*16*32 = 4096          (per-warp partials)
    float* gate = red + 8 * 16 * 32;     // 16*32   = 512
    float* c_s  = gate + 16 * 32;        // 4*32    = 128           (cell state, persistent)

    const int tid = threadIdx.x;
    const int cta = blockIdx.x;          // 0..127 -> units [cta*4, cta*4+4)

    // One-time: load 16 gate rows of Whh, transposed into [k][lr]
    for (int idx = tid; idx < 16 * 512; idx += 256) {
        int lrw = idx >> 9;              // 0..15
        int k   = idx & 511;
        int q = lrw >> 2, u = lrw & 3;
        int row = q * 512 + cta * 4 + u;
        w_s[k * 16 + lrw] = Whh_l[(size_t)row * 512 + k];
    }
    if (tid < 128) c_s[tid] = 0.f;
    __syncthreads();

    const int lane = tid & 31, warp = tid >> 5;
    const int rg = lane >> 3, bg = lane & 7;
    const int k0 = warp * 64;

    // Reduce-phase output assignment (2 per thread)
    const int o0 = tid, o1 = tid + 256;
    const int lr0 = o0 >> 5, b0 = o0 & 31;
    const int lr1 = o1 >> 5, b1 = o1 & 31;
    const int row0 = (lr0 >> 2) * 512 + cta * 4 + (lr0 & 3);
    const int row1 = (lr1 >> 2) * 512 + cta * 4 + (lr1 & 3);

    for (int t = 0; t < NL; t++) {
        // Prefetch xg for this step (independent of h -> overlaps dot products)
        float xg0 = __ldg(g_xg + (size_t)(t * 32 + b0) * NG + row0);
        float xg1 = __ldg(g_xg + (size_t)(t * 32 + b1) * NG + row1);

        // Stage h_{t-1} into smem
        const float* hsrc = g_hstate + (t & 1) * NH * NB;
        for (int i = tid * 4; i < 512 * 32; i += 256 * 4)
            *(float4*)(hs + i) = *(const float4*)(hsrc + i);
        __syncthreads();

        // Dot products: this warp handles K in [k0, k0+64)
        float acc[4][4];
#pragma unroll
        for (int i = 0; i < 4; i++)
#pragma unroll
            for (int j = 0; j < 4; j++) acc[i][j] = 0.f;

#pragma unroll 4
        for (int k = k0; k < k0 + 64; k++) {
            float4 wv = *(const float4*)(w_s + k * 16 + rg * 4);
            float4 hv = *(const float4*)(hs  + k * 32 + bg * 4);
            acc[0][0] += wv.x * hv.x; acc[0][1] += wv.x * hv.y;
            acc[0][2] += wv.x * hv.z; acc[0][3] += wv.x * hv.w;
            acc[1][0] += wv.y * hv.x; acc[1][1] += wv.y * hv.y;
            acc[1][2] += wv.y * hv.z; acc[1][3] += wv.y * hv.w;
            acc[2][0] += wv.z * hv.x; acc[2][1] += wv.z * hv.y;
            acc[2][2] += wv.z * hv.z; acc[2][3] += wv.z * hv.w;
            acc[3][0] += wv.w * hv.x; acc[3][1] += wv.w * hv.y;
            acc[3][2] += wv.w * hv.z; acc[3][3] += wv.w * hv.w;
        }
#pragma unroll
        for (int ri = 0; ri < 4; ri++)
            *(float4*)(red + ((warp * 16 + rg * 4 + ri) * 32 + bg * 4)) =
                make_float4(acc[ri][0], acc[ri][1], acc[ri][2], acc[ri][3]);
        __syncthreads();

        // Cross-warp K reduction + add xg (bias already in xg)
        {
            float s0 = xg0, s1 = xg1;
#pragma unroll
            for (int w = 0; w < 8; w++) {
                s0 += red[(w * 16 + lr0) * 32 + b0];
                s1 += red[(w * 16 + lr1) * 32 + b1];
            }
            gate[lr0 * 32 + b0] = s0;
            gate[lr1 * 32 + b1] = s1;
        }
        __syncthreads();

        // Gates + state update (torch order i, f, g, o; lr = q*4 + u)
        if (tid < 128) {
            int u = tid >> 5, b = tid & 31;
            float gi = gate[(0 + u) * 32 + b];
            float gf = gate[(4 + u) * 32 + b];
            float gg = gate[(8 + u) * 32 + b];
            float go = gate[(12 + u) * 32 + b];
            float ig = 1.f / (1.f + __expf(-gi));
            float fg = 1.f / (1.f + __expf(-gf));
            float cg = tanhf(gg);
            float og = 1.f / (1.f + __expf(-go));
            float c = fg * c_s[tid] + ig * cg;
            c_s[tid] = c;
            float h = og * tanhf(c);
            int j = cta * 4 + u;
            g_hstate[((t + 1) & 1) * NH * NB + j * 32 + b] = h;
            if (write_seq) g_hseq[(size_t)(t * 32 + b) * NH + j] = h;
            if (t == NL - 1) {
                d_out[layer * NB * NH + b * NH + j] = h;                       // hidden
                d_out[NLAYERS * NB * NH + layer * NB * NH + b * NH + j] = c;   // cell
            }
        }
        __syncthreads();

        // Grid-wide barrier (release-acquire via fence + monotonic counter)
        if (tid == 0) {
            __threadfence();
            atomicAdd(&g_bar, 1);
            int target = 128 * (t + 1);
            int v;
            do {
                asm volatile("ld.acquire.gpu.s32 %0, [%1];" : "=r"(v) : "l"(&g_bar));
            } while (v < target);
        }
        __syncthreads();
    }
}

// ---------------------------------------------------------------------------
// Launcher
// ---------------------------------------------------------------------------
extern "C" void kernel_launch(void* const* d_in, const int* in_sizes, int n_in,
                              void* d_out, int out_size) {
    const int*   tokens = (const int*)  d_in[0];
    const float* emb    = (const float*)d_in[1];
    const float* Wih    = (const float*)d_in[2];   // (2, 2048, 512)
    const float* Whh    = (const float*)d_in[3];   // (2, 2048, 512)
    const float* bih    = (const float*)d_in[4];   // (2, 2048)
    const float* bhh    = (const float*)d_in[5];   // (2, 2048)
    float* out = (float*)d_out;

    const int REC_SMEM = (512 * 32 + 512 * 16 + 8 * 16 * 32 + 16 * 32 + 4 * 32) * 4;
    cudaFuncSetAttribute(lstm_rec, cudaFuncAttributeMaxDynamicSharedMemorySize, REC_SMEM);

    dim3 ggrid(NG / 128, (NL * NB) / 128);   // (16, 128)

    // ---- layer 0 ----
    xg_gemm<<<ggrid, 256>>>(emb, tokens, 1, Wih, bih, bhh);
    init_kernel<<<1, 256>>>();
    lstm_rec<<<128, 256, REC_SMEM>>>(Whh, 1, 0, out);

    // ---- layer 1 ----
    xg_gemm<<<ggrid, 256>>>(emb, tokens, 0, Wih + (size_t)NG * NH, bih + NG, bhh + NG);
    init_kernel<<<1, 256>>>();
    lstm_rec<<<128, 256, REC_SMEM>>>(Whh + (size_t)NG * NH, 0, 1, out);
}